// round 2
// baseline (speedup 1.0000x reference)
#include <cuda_runtime.h>
#include <math.h>

#define SEQ 512
#define BSZ 128
#define EMBD 128
#define HID 128
#define HG  512     // 4*H
#define TAGS 7
#define BOS 4
#define EOS 5

// ---------------- scratch (static device arrays; no allocation) ----------------
__device__ float g_xw[2][SEQ][BSZ][HG];    // input projections (both dirs), 256 MiB
__device__ float g_hs[2][SEQ][BSZ][HID];   // hidden states fwd/bwd, 64 MiB
__device__ float g_fts[SEQ][BSZ][8];       // tag logits (padded to 8)

__device__ __forceinline__ float sigf(float x) { return 1.0f / (1.0f + expf(-x)); }

// ================= K1: embedding gather + input projection GEMM =================
// out[row=s*128+b][col=dir*512+g] = emb[sen[row]] . Wih_dir[g] + b_dir[g]
// 64x64 tile, BK=32, 256 threads, 4x4 per thread. FFMA-bound.
__global__ __launch_bounds__(256) void k_inproj(
    const int* __restrict__ sen, const float* __restrict__ emb,
    const float* __restrict__ Wf, const float* __restrict__ bf,
    const float* __restrict__ Wb, const float* __restrict__ bb)
{
    __shared__ float As[32][64];   // k-major A tile
    __shared__ float Bs[32][64];   // k-major B tile
    __shared__ int   tok[64];

    const int tid = threadIdx.x;
    const int row0 = blockIdx.x * 64;
    const int col0 = blockIdx.y * 64;           // global col in [0,1024)
    const int dir  = col0 >> 9;
    const int g0   = col0 & 511;
    const float* __restrict__ W    = dir ? Wb : Wf;
    const float* __restrict__ bias = dir ? bb : bf;

    if (tid < 64) tok[tid] = sen[row0 + tid];
    __syncthreads();

    float acc[4][4];
#pragma unroll
    for (int i = 0; i < 4; i++)
#pragma unroll
        for (int j = 0; j < 4; j++) acc[i][j] = 0.0f;

    const int ty = tid >> 4, tx = tid & 15;
    const int lr = tid >> 2;              // 0..63 (row / col for staging)
    const int kp = (tid & 3) * 8;         // 0,8,16,24

    for (int kc = 0; kc < 128; kc += 32) {
        // stage A (gathered embedding rows), transposed to k-major
        {
            const float* src = emb + (long)tok[lr] * EMBD + kc + kp;
            float4 v0 = *(const float4*)(src);
            float4 v1 = *(const float4*)(src + 4);
            As[kp + 0][lr] = v0.x; As[kp + 1][lr] = v0.y;
            As[kp + 2][lr] = v0.z; As[kp + 3][lr] = v0.w;
            As[kp + 4][lr] = v1.x; As[kp + 5][lr] = v1.y;
            As[kp + 6][lr] = v1.z; As[kp + 7][lr] = v1.w;
        }
        // stage B (weights), transposed to k-major
        {
            const float* src = W + (long)(g0 + lr) * EMBD + kc + kp;
            float4 v0 = *(const float4*)(src);
            float4 v1 = *(const float4*)(src + 4);
            Bs[kp + 0][lr] = v0.x; Bs[kp + 1][lr] = v0.y;
            Bs[kp + 2][lr] = v0.z; Bs[kp + 3][lr] = v0.w;
            Bs[kp + 4][lr] = v1.x; Bs[kp + 5][lr] = v1.y;
            Bs[kp + 6][lr] = v1.z; Bs[kp + 7][lr] = v1.w;
        }
        __syncthreads();
#pragma unroll
        for (int k = 0; k < 32; k++) {
            float4 a = *(const float4*)&As[k][ty * 4];
            float4 b = *(const float4*)&Bs[k][tx * 4];
            float av[4] = {a.x, a.y, a.z, a.w};
            float bv[4] = {b.x, b.y, b.z, b.w};
#pragma unroll
            for (int i = 0; i < 4; i++)
#pragma unroll
                for (int j = 0; j < 4; j++) acc[i][j] += av[i] * bv[j];
        }
        __syncthreads();
    }

    float4 bi = *(const float4*)&bias[g0 + tx * 4];
#pragma unroll
    for (int i = 0; i < 4; i++) {
        int R = row0 + ty * 4 + i;
        int s = R >> 7, b = R & 127;
        float4 o;
        o.x = acc[i][0] + bi.x;
        o.y = acc[i][1] + bi.y;
        o.z = acc[i][2] + bi.z;
        o.w = acc[i][3] + bi.w;
        *(float4*)&g_xw[dir][s][b][g0 + tx * 4] = o;
    }
}

// ================= K2: LSTM recurrence, both directions =================
// 128 blocks: dir = bid>>6, batch pair = (bid&63)*2. 512 threads = one gate row each,
// 2 batch elems per weight read (weights streamed from global through L1 each step).
__global__ __launch_bounds__(512) void k_lstm(
    const float* __restrict__ Whh_f, const float* __restrict__ Whh_b)
{
    const int bid = blockIdx.x;
    const int dir = bid >> 6;
    const int b0  = (bid & 63) * 2;
    const float* __restrict__ Whh = dir ? Whh_b : Whh_f;

    const int t = threadIdx.x;
    __shared__ float2 hsm[HID];     // h for both batch elems
    __shared__ float2 gbuf[HG];     // raw gate preactivations

    if (t < HID) hsm[t] = make_float2(0.0f, 0.0f);
    float c0 = 0.0f, c1 = 0.0f;
    __syncthreads();

    const float4* __restrict__ w4 = (const float4*)(Whh + t * HID);
    const float4* h4 = (const float4*)hsm;

    for (int step = 0; step < SEQ; ++step) {
        const int s = dir ? (SEQ - 1 - step) : step;
        const float* xwp = &g_xw[dir][s][b0][0];
        float xw0 = xwp[t];
        float xw1 = xwp[HG + t];

        float a0 = 0.0f, a1 = 0.0f;
#pragma unroll
        for (int k = 0; k < 32; k++) {
            float4 w = w4[k];
            float4 p = h4[2 * k];
            float4 q = h4[2 * k + 1];
            a0 += w.x * p.x; a1 += w.x * p.y;
            a0 += w.y * p.z; a1 += w.y * p.w;
            a0 += w.z * q.x; a1 += w.z * q.y;
            a0 += w.w * q.z; a1 += w.w * q.w;
        }
        gbuf[t] = make_float2(a0 + xw0, a1 + xw1);
        __syncthreads();

        if (t < HID) {
            float2 gi = gbuf[t];
            float2 gf = gbuf[t + 128];
            float2 gg = gbuf[t + 256];
            float2 go = gbuf[t + 384];

            c0 = sigf(gf.x) * c0 + sigf(gi.x) * tanhf(gg.x);
            c1 = sigf(gf.y) * c1 + sigf(gi.y) * tanhf(gg.y);
            float nh0 = sigf(go.x) * tanhf(c0);
            float nh1 = sigf(go.y) * tanhf(c1);

            hsm[t] = make_float2(nh0, nh1);
            float* hd = &g_hs[dir][s][b0][0];
            hd[t] = nh0;
            hd[HID + t] = nh1;
        }
        __syncthreads();
    }
}

// ================= K3: hid2tag logits =================
// 8 warps/block, each warp one (s,b) row. fts = [hf|hb] . W_out^T + b_out
__global__ __launch_bounds__(256) void k_fts(
    const float* __restrict__ W_out, const float* __restrict__ b_out)
{
    __shared__ float Ws[TAGS * 256];
    __shared__ float bs[TAGS];
    const int tid = threadIdx.x;
    for (int i = tid; i < TAGS * 256; i += 256) Ws[i] = W_out[i];
    if (tid < TAGS) bs[tid] = b_out[tid];
    __syncthreads();

    const int warp = tid >> 5, lane = tid & 31;
    const int rb = blockIdx.x * 8 + warp;   // 0..65535
    const int s = rb >> 7, b = rb & 127;

    float4 hf = ((const float4*)&g_hs[0][s][b][0])[lane];
    float4 hb = ((const float4*)&g_hs[1][s][b][0])[lane];

    float mine = 0.0f;
#pragma unroll
    for (int T = 0; T < TAGS; T++) {
        const float* w = &Ws[T * 256];
        float4 wa = *(const float4*)&w[lane * 4];
        float4 wb = *(const float4*)&w[128 + lane * 4];
        float p = hf.x * wa.x + hf.y * wa.y + hf.z * wa.z + hf.w * wa.w
                + hb.x * wb.x + hb.y * wb.y + hb.z * wb.z + hb.w * wb.w;
#pragma unroll
        for (int o = 16; o > 0; o >>= 1) p += __shfl_xor_sync(0xffffffffu, p, o);
        if (lane == T) mine = p;
    }
    if (lane < TAGS) g_fts[s][b][lane] = mine + bs[lane];
}

// ================= K4: Viterbi forward + backtrace (one block per batch) =================
__global__ __launch_bounds__(64) void k_viterbi(
    const float* __restrict__ trans, float* __restrict__ out, int out_size)
{
    const int b = blockIdx.x;
    __shared__ float sft[SEQ][TAGS];
    __shared__ unsigned char bp[SEQ][8];
    const int tid = threadIdx.x;

    for (int i = tid; i < SEQ * TAGS; i += 64) {
        int s = i / TAGS, T = i % TAGS;
        sft[s][T] = g_fts[s][b][T];
    }
    __syncthreads();
    if (tid >= 32) return;

    const int lane = tid;
    const int j = (lane < TAGS) ? lane : (TAGS - 1);
    float tr[TAGS];
#pragma unroll
    for (int p = 0; p < TAGS; p++) tr[p] = trans[j * TAGS + p];

    float fv = (lane == BOS) ? 0.0f : -10000.0f;

    for (int s = 0; s < SEQ; s++) {
        float best = -3.4e38f;
        int bi = 0;
#pragma unroll
        for (int p = 0; p < TAGS; p++) {
            float fvp = __shfl_sync(0xffffffffu, fv, p);
            float sc = fvp + tr[p];
            if (sc > best) { best = sc; bi = p; }   // strict > : first-max like jnp.argmax
        }
        if (lane < TAGS) {
            bp[s][lane] = (unsigned char)bi;
            fv = best + sft[s][lane];
        }
    }

    float term = fv + trans[EOS * TAGS + j];
    float bestv = -3.4e38f;
    int bidx = 0;
#pragma unroll
    for (int p = 0; p < TAGS; p++) {
        float tv = __shfl_sync(0xffffffffu, term, p);
        if (tv > bestv) { bestv = tv; bidx = p; }
    }

    if (lane == 0) {
        int tagbase = -1;
        bool write_score = false;
        if (out_size >= 128 + SEQ * BSZ) { write_score = true; tagbase = 128; }
        else if (out_size >= SEQ * BSZ)  { tagbase = 0; }
        else                             { write_score = true; }

        if (write_score) out[b] = bestv;
        if (tagbase >= 0) {
            int cur = bidx;
            for (int s = SEQ - 1; s >= 0; s--) {
                out[tagbase + s * BSZ + b] = (float)cur;
                cur = bp[s][cur];
            }
        }
    }
}

// ================= launcher =================
extern "C" void kernel_launch(void* const* d_in, const int* in_sizes, int n_in,
                              void* d_out, int out_size)
{
    const int*   sen   = (const int*)  d_in[0];
    const float* emb   = (const float*)d_in[1];
    const float* Wih_f = (const float*)d_in[2];
    const float* Whh_f = (const float*)d_in[3];
    const float* b_f   = (const float*)d_in[4];
    const float* Wih_b = (const float*)d_in[5];
    const float* Whh_b = (const float*)d_in[6];
    const float* b_b   = (const float*)d_in[7];
    const float* W_out = (const float*)d_in[8];
    const float* b_out = (const float*)d_in[9];
    const float* trans = (const float*)d_in[10];
    float* out = (float*)d_out;

    dim3 g1(1024, 16);
    k_inproj<<<g1, 256>>>(sen, emb, Wih_f, b_f, Wih_b, b_b);
    k_lstm<<<128, 512>>>(Whh_f, Whh_b);
    k_fts<<<8192, 256>>>(W_out, b_out);
    k_viterbi<<<128, 64>>>(trans, out, out_size);
}